// round 12
// baseline (speedup 1.0000x reference)
#include <cuda_runtime.h>

// ---------------------------------------------------------------------------
// out[i, j] = f(j-1) - f(j),  f(j) = relu(1 - relu(x_full[j+1] - x_i) /
//                                         (x_full[j+1] - x_full[j] + 1e-9))
// sentinels f(-1)=1, f(n_full-1)=0; nonzeros only in j in [k-2, k+5].
// ONE kernel (every extra launch costs ~5us wall, measured R1..R11), one
// float4 chunk per thread (best store-stream shape):
//   1. STG.128 zero UNCONDITIONALLY -> store stream has no load deps (this
//      is what killed R8: its single store waited on the window-test loads)
//   2. window test (2 broadcast LDGs) runs behind the store
//   3. rare hit (~1.5%): store exact float4 over the zero (same thread,
//      program order => patch wins)
// ---------------------------------------------------------------------------

__device__ __forceinline__ float evalf_g(const float* __restrict__ xf,
                                         int j, int n, float x) {
    if (j < 0) return 1.0f;
    if (j >= n - 1) return 0.0f;
    float xa = __ldg(xf + j);
    float xb = __ldg(xf + j + 1);
    float t  = fmaxf(0.f, xb - x);
    return fmaxf(0.f, 1.0f - t / (xb - xa + 1e-9f));
}

__device__ __forceinline__ float value_g(const float* __restrict__ xf,
                                         int c, int n, float x) {
    return evalf_g(xf, c - 1, n, x) - evalf_g(xf, c, n, x);
}

__global__ void __launch_bounds__(256)
fused_kernel(const float* __restrict__ x_eval,
             const float* __restrict__ x_full,
             float* __restrict__ out,
             int n_full, int n4, int tail,
             unsigned magic, int mshift) {
    int t = blockIdx.x * blockDim.x + threadIdx.x;
    if (t >= n4) {
        if (t == n4 && tail) {                     // scalar tail thread
            for (int e = 0; e < tail; ++e) {
                int p  = n4 * 4 + e;
                int rr = (int)(__umulhi((unsigned)p, magic) >> mshift);
                int cc = p - rr * n_full;
                if (cc >= n_full) { cc -= n_full; ++rr; }
                out[p] = value_g(x_full, cc, n_full, __ldg(x_eval + rr));
            }
        }
        return;
    }

    // 1) unconditional zero store: zero-dependency, full-rate stream
    __stcs(reinterpret_cast<float4*>(out) + t,
           make_float4(0.f, 0.f, 0.f, 0.f));

    // 2) locate chunk and test the window (loads trail the store)
    int p  = t << 2;
    int rr = (int)(__umulhi((unsigned)p, magic) >> mshift);
    int cc = p - rr * n_full;
    if (cc >= n_full) { cc -= n_full; ++rr; }      // floor-magic fixup (<=1)

    float x = __ldg(x_eval + rr);                  // broadcast within row

    int ilo = cc - 6;  if (ilo < 0) ilo = 0;       // covers [k-2,k+5] + eps
    int ihi = cc + 7;  if (ihi > n_full - 1) ihi = n_full - 1;
    float xlo = __ldg(x_full + ilo);
    float xhi = __ldg(x_full + ihi);

    bool edge = (cc < 12) | (cc > n_full - 13);    // clamped bounds -> slow
    bool slow = edge | ((x >= xlo) & (x <= xhi));

    // 3) rare patch: exact formula for the 4 columns (may straddle rows)
    if (slow) {
        float4 v;
        #pragma unroll
        for (int e = 0; e < 4; ++e) {
            int pe = p + e;
            int re = rr, ce = cc + e;
            if (ce >= n_full) { ce -= n_full; ++re; }
            float xe = (re == rr) ? x : __ldg(x_eval + re);
            ((float*)&v)[e] = value_g(x_full, ce, n_full, xe);
        }
        __stcs(reinterpret_cast<float4*>(out) + t, v);   // overwrites zero
    }
}

extern "C" void kernel_launch(void* const* d_in, const int* in_sizes, int n_in,
                              void* d_out, int out_size) {
    const float* x_eval = (const float*)d_in[0];  // (n_points, 1) float32
    const float* x_full = (const float*)d_in[1];  // (n_full,)    float32 sorted
    float* out = (float*)d_out;                   // (n_points, n_full) float32

    int n_full = in_sizes[1];

    int total = out_size;
    int n4    = total >> 2;
    int tail  = total & 3;

    // floor magic for division by n_full (p < 2^31)
    int s = 0;
    while ((1ull << (32 + s)) / (unsigned)n_full < (1ull << 31)) ++s;
    unsigned magic = (unsigned)((1ull << (32 + s)) / (unsigned)n_full);

    int threads = 256;
    int blocks  = (n4 + 1 + threads - 1) / threads;   // +1 covers tail thread
    fused_kernel<<<blocks, threads>>>(x_eval, x_full, out,
                                      n_full, n4, tail, magic, s);
}

// round 14
// speedup vs baseline: 1.4581x; 1.4581x over previous
#include <cuda_runtime.h>

// ---------------------------------------------------------------------------
// out[i, j] = f(j-1) - f(j),  f(j) = relu(1 - relu(x_full[j+1] - x_i) /
//                                         (x_full[j+1] - x_full[j] + 1e-9))
// sentinels f(-1)=1, f(n_full-1)=0; nonzeros only in j in [k-2, k+5].
// R14: cudaMemsetAsync zero-fill (graph memset node; float 0.0f == all-zero
// bytes) + warp-per-row scatter.  Search = interpolation guess with a
// DIRECTION LATCH (fixes R13's boundary ping-pong: once we've moved right,
// an all-greater window pins k0 = base-1, and symmetrically left), so it
// provably terminates; typically 1 probe round (x_full ~ Uniform[0,1]).
// ---------------------------------------------------------------------------

__device__ __forceinline__ float evalf_g(const float* __restrict__ xf,
                                         int j, int n, float x) {
    if (j < 0) return 1.0f;
    if (j >= n - 1) return 0.0f;
    float xa = __ldg(xf + j);
    float xb = __ldg(xf + j + 1);
    float t  = fmaxf(0.f, xb - x);
    return fmaxf(0.f, 1.0f - t / (xb - xa + 1e-9f));
}

__global__ void __launch_bounds__(256)
scatter_kernel(const float* __restrict__ x_eval,
               const float* __restrict__ x_full,
               float* __restrict__ out,
               int n_points, int n_full) {
    int gwarp = (blockIdx.x * blockDim.x + threadIdx.x) >> 5;
    int lane  = threadIdx.x & 31;
    if (gwarp >= n_points) return;

    float x = __ldg(x_eval + gwarp);
    int n = n_full;

    // ---- guess + latched ballot search: k0 = max{m : x_full[m] <= x} -----
    const unsigned FULL = 0xffffffffu;
    int guess = (int)(x * (float)(n - 1));
    if (guess < 0) guess = 0;
    if (guess > n - 1) guess = n - 1;
    int base = guess - 15;
    int dir  = 0;                                   // 0 none, +1 right, -1 left
    int k0;
    while (true) {
        int m  = base + lane;
        int mc = m < 0 ? 0 : (m > n - 1 ? n - 1 : m);
        bool t = (m < 0) ? true                     // virtual -inf knot
               : (m > n - 1) ? false                // virtual +inf knot
               : (__ldg(x_full + mc) <= x);
        unsigned b = __ballot_sync(FULL, t);
        if (b == FULL) {                            // whole window <= x
            if (dir < 0)            { k0 = base + 31; break; }  // crossed back
            if (base + 31 >= n - 1) { k0 = n - 1;    break; }
            dir = 1;  base += 32;
        } else if (b == 0u) {                       // whole window > x
            if (dir > 0)  { k0 = base - 1; break; } // crossed back
            if (base <= 0){ k0 = -1;       break; }
            dir = -1; base -= 32;
        } else {                                    // transition inside window
            k0 = base + (31 - __clz(b));
            break;
        }
    }

    int k = k0 < 0 ? 0 : k0;
    if (k > n - 2) k = n - 2;
    int j0 = (k - 2 < 0) ? 0 : (k - 2);
    int j1 = (k + 5 > n - 1) ? (n - 1) : (k + 5);
    int cnt = j1 - j0 + 1;                          // <= 8

    if (lane < cnt) {
        int c = j0 + lane;
        float v = evalf_g(x_full, c - 1, n, x) - evalf_g(x_full, c, n, x);
        out[gwarp * n + c] = v;
    }
}

extern "C" void kernel_launch(void* const* d_in, const int* in_sizes, int n_in,
                              void* d_out, int out_size) {
    const float* x_eval = (const float*)d_in[0];  // (n_points, 1) float32
    const float* x_full = (const float*)d_in[1];  // (n_full,)    float32 sorted
    float* out = (float*)d_out;                   // (n_points, n_full) float32

    int n_points = in_sizes[0];
    int n_full   = in_sizes[1];

    // 1) zero-fill via the driver's fill path (async -> graph memset node)
    cudaMemsetAsync(out, 0, (size_t)out_size * sizeof(float), 0);

    // 2) scatter the <=8 window elements per row (1 warp/row)
    int threads = 256;
    int blocks  = (n_points * 32 + threads - 1) / threads;
    scatter_kernel<<<blocks, threads>>>(x_eval, x_full, out,
                                        n_points, n_full);
}

// round 15
// speedup vs baseline: 1.5341x; 1.0522x over previous
#include <cuda_runtime.h>

// ---------------------------------------------------------------------------
// out[i, j] = f(j-1) - f(j),  f(j) = relu(1 - relu(x_full[j+1] - x_i) /
//                                         (x_full[j+1] - x_full[j] + 1e-9))
// sentinels f(-1)=1, f(n_full-1)=0; nonzeros only in j in [k-2, k+5].
// R15: the end-to-end write rate (~5.7 TB/s incl. L2 drain) is the binding
// constraint.  Test 256-bit stores (st.global.cs.v8.f32, sm_100+): half the
// store instructions, double the bytes per wavefront.  Scatter unchanged
// (its wall is the L2 writeback drain, not its own work).
// ---------------------------------------------------------------------------

__global__ void __launch_bounds__(256)
zero_kernel(float* __restrict__ out, int n8, int rem) {
    int i = blockIdx.x * blockDim.x + threadIdx.x;
    if (i < n8) {
        float z = 0.f;
        asm volatile(
            "st.global.cs.v8.f32 [%0], {%1,%1,%1,%1,%1,%1,%1,%1};"
            :: "l"(out + (size_t)i * 8), "f"(z) : "memory");
    }
    if (i == 0) {
        for (int r = 0; r < rem; ++r) out[(size_t)n8 * 8 + r] = 0.f;
    }
}

__device__ __forceinline__ float evalf_g(const float* __restrict__ xf,
                                         int j, int n, float x) {
    if (j < 0) return 1.0f;
    if (j >= n - 1) return 0.0f;
    float xa = __ldg(xf + j);
    float xb = __ldg(xf + j + 1);
    float t  = fmaxf(0.f, xb - x);
    return fmaxf(0.f, 1.0f - t / (xb - xa + 1e-9f));
}

__global__ void __launch_bounds__(256)
scatter_kernel(const float* __restrict__ x_eval,
               const float* __restrict__ x_full,
               float* __restrict__ out,
               int n_points, int n_full) {
    int gwarp = (blockIdx.x * blockDim.x + threadIdx.x) >> 5;
    int lane  = threadIdx.x & 31;
    if (gwarp >= n_points) return;

    float x = __ldg(x_eval + gwarp);
    int n = n_full;

    // guess + direction-latched ballot search: k0 = max{m : x_full[m] <= x}
    const unsigned FULL = 0xffffffffu;
    int guess = (int)(x * (float)(n - 1));
    if (guess < 0) guess = 0;
    if (guess > n - 1) guess = n - 1;
    int base = guess - 15;
    int dir  = 0;
    int k0;
    while (true) {
        int m  = base + lane;
        int mc = m < 0 ? 0 : (m > n - 1 ? n - 1 : m);
        bool t = (m < 0) ? true
               : (m > n - 1) ? false
               : (__ldg(x_full + mc) <= x);
        unsigned b = __ballot_sync(FULL, t);
        if (b == FULL) {
            if (dir < 0)            { k0 = base + 31; break; }
            if (base + 31 >= n - 1) { k0 = n - 1;    break; }
            dir = 1;  base += 32;
        } else if (b == 0u) {
            if (dir > 0)  { k0 = base - 1; break; }
            if (base <= 0){ k0 = -1;       break; }
            dir = -1; base -= 32;
        } else {
            k0 = base + (31 - __clz(b));
            break;
        }
    }

    int k = k0 < 0 ? 0 : k0;
    if (k > n - 2) k = n - 2;
    int j0 = (k - 2 < 0) ? 0 : (k - 2);
    int j1 = (k + 5 > n - 1) ? (n - 1) : (k + 5);
    int cnt = j1 - j0 + 1;                          // <= 8

    if (lane < cnt) {
        int c = j0 + lane;
        float v = evalf_g(x_full, c - 1, n, x) - evalf_g(x_full, c, n, x);
        out[gwarp * n + c] = v;
    }
}

extern "C" void kernel_launch(void* const* d_in, const int* in_sizes, int n_in,
                              void* d_out, int out_size) {
    const float* x_eval = (const float*)d_in[0];  // (n_points, 1) float32
    const float* x_full = (const float*)d_in[1];  // (n_full,)    float32 sorted
    float* out = (float*)d_out;                   // (n_points, n_full) float32

    int n_points = in_sizes[0];
    int n_full   = in_sizes[1];

    // 1) zero-fill with 256-bit streaming stores
    int n8  = out_size >> 3;
    int rem = out_size & 7;
    int zb  = (n8 + 255) / 256;
    if (zb < 1) zb = 1;
    zero_kernel<<<zb, 256>>>(out, n8, rem);

    // 2) scatter the <=8 window elements per row (1 warp/row)
    int threads = 256;
    int blocks  = (n_points * 32 + threads - 1) / threads;
    scatter_kernel<<<blocks, threads>>>(x_eval, x_full, out,
                                        n_points, n_full);
}